// round 1
// baseline (speedup 1.0000x reference)
#include <cuda_runtime.h>
#include <math.h>

#define BATCH   2
#define LSEQ    1024
#define DMODEL  2048
#define DINNER  4096
#define DSTATE  16
#define DTRANK  128
#define KCONV   4
#define MROWS   (BATCH*LSEQ)          // 2048
#define E2      (2*DINNER)            // 8192
#define XDBL_C  (DTRANK + 2*DSTATE)   // 160
#define NCHUNK  16
#define CLEN    (LSEQ/NCHUNK)         // 64

// -------- scratch (static device globals; no allocation anywhere) ----------
__device__ __align__(16) float g_xz   [(size_t)MROWS * E2];      // (m, e)  e-contig: x = e<4096, z = e>=4096
__device__ __align__(16) float g_xc   [(size_t)MROWS * DINNER];  // silu(conv(x)) in (m, d)
__device__ __align__(16) float g_xdbl [(size_t)MROWS * XDBL_C];  // (m, 160): dt|B|C
__device__ __align__(16) float g_delta[(size_t)MROWS * DINNER];  // softplus(dt2+b_dt), (m, d)
__device__ __align__(16) float g_y    [(size_t)MROWS * DINNER];  // scan output, (m, d)
__device__ __align__(16) float g_cA   [(size_t)BATCH*NCHUNK*DSTATE*DINNER];
__device__ __align__(16) float g_cS   [(size_t)BATCH*NCHUNK*DSTATE*DINNER];
__device__ __align__(16) float g_sini [(size_t)BATCH*NCHUNK*DSTATE*DINNER];

// ---------------------------------------------------------------------------
// Generic NT fp32 GEMM: C[i,j] = sum_k A[i*lda+k] * B[j*ldb+k]  (+ epilogue)
// 128x128 tile, BK=8, 256 threads, 8x8 per thread, float4 smem paths.
// EPI: 0 = none, 1 = softplus(v + bias[j]), 2 = v + bias[j]
// ---------------------------------------------------------------------------
template<int EPI>
__global__ void __launch_bounds__(256, 2) gemm_nt(
    int M, int N, int K,
    const float* __restrict__ A, int lda,
    const float* __restrict__ B, int ldb,
    float* __restrict__ C, int ldc,
    const float* __restrict__ bias)
{
    __shared__ float As[8][128];
    __shared__ float Bs[8][128];

    const int tid  = threadIdx.x;
    const int tx   = tid & 15;          // 0..15 -> col groups of 8
    const int ty   = tid >> 4;          // 0..15 -> row groups of 8
    const int row0 = blockIdx.y * 128;
    const int col0 = blockIdx.x * 128;

    const int ldRow = tid >> 1;         // 0..127
    const int ldCol = (tid & 1) * 4;    // 0 or 4

    const float* Ap = A + (size_t)(row0 + ldRow) * lda + ldCol;
    const float* Bp = B + (size_t)(col0 + ldRow) * ldb + ldCol;
    const bool aOk = (row0 + ldRow) < M;
    const bool bOk = (col0 + ldRow) < N;

    float acc[8][8];
    #pragma unroll
    for (int i = 0; i < 8; i++)
        #pragma unroll
        for (int j = 0; j < 8; j++) acc[i][j] = 0.f;

    for (int k0 = 0; k0 < K; k0 += 8) {
        float4 a4 = aOk ? *(const float4*)Ap : make_float4(0.f,0.f,0.f,0.f);
        float4 b4 = bOk ? *(const float4*)Bp : make_float4(0.f,0.f,0.f,0.f);
        Ap += 8; Bp += 8;
        __syncthreads();
        As[ldCol+0][ldRow] = a4.x; As[ldCol+1][ldRow] = a4.y;
        As[ldCol+2][ldRow] = a4.z; As[ldCol+3][ldRow] = a4.w;
        Bs[ldCol+0][ldRow] = b4.x; Bs[ldCol+1][ldRow] = b4.y;
        Bs[ldCol+2][ldRow] = b4.z; Bs[ldCol+3][ldRow] = b4.w;
        __syncthreads();
        #pragma unroll
        for (int k = 0; k < 8; k++) {
            float ar[8], br[8];
            *(float4*)&ar[0] = *(const float4*)&As[k][ty*8];
            *(float4*)&ar[4] = *(const float4*)&As[k][ty*8 + 4];
            *(float4*)&br[0] = *(const float4*)&Bs[k][tx*8];
            *(float4*)&br[4] = *(const float4*)&Bs[k][tx*8 + 4];
            #pragma unroll
            for (int i = 0; i < 8; i++)
                #pragma unroll
                for (int j = 0; j < 8; j++)
                    acc[i][j] = fmaf(ar[i], br[j], acc[i][j]);
        }
    }

    #pragma unroll
    for (int i = 0; i < 8; i++) {
        int r = row0 + ty*8 + i;
        if (r >= M) continue;
        #pragma unroll
        for (int j = 0; j < 8; j++) {
            int c2 = col0 + tx*8 + j;
            if (c2 >= N) continue;
            float v = acc[i][j];
            if (EPI == 1) {            // softplus(v + b_dt)
                v += bias[c2];
                v = (v > 20.f) ? v : log1pf(__expf(v));
            } else if (EPI == 2) {     // + b_out
                v += bias[c2];
            }
            C[(size_t)r * ldc + c2] = v;
        }
    }
}

// ---------------------------------------------------------------------------
// Depthwise causal conv (K=4) + SiLU.  x lives in g_xz (e < DINNER), l-major
// rows with stride E2; output g_xc (m, d). Coalesced over d.
// ---------------------------------------------------------------------------
__global__ void conv_silu_kernel(const float* __restrict__ conv_w,
                                 const float* __restrict__ conv_b)
{
    const int d  = blockIdx.x * 256 + threadIdx.x;     // 0..4095
    const int b  = blockIdx.z;
    const int l0 = blockIdx.y * 128;

    const float w0 = conv_w[d*4+0], w1 = conv_w[d*4+1];
    const float w2 = conv_w[d*4+2], w3 = conv_w[d*4+3];
    const float cb = conv_b[d];

    const float* xb = g_xz + (size_t)b * LSEQ * E2 + d;
    float*       ob = g_xc + (size_t)b * LSEQ * DINNER + d;

    float x0 = (l0 >= 3) ? xb[(size_t)(l0-3) * E2] : 0.f;
    float x1 = (l0 >= 2) ? xb[(size_t)(l0-2) * E2] : 0.f;
    float x2 = (l0 >= 1) ? xb[(size_t)(l0-1) * E2] : 0.f;

    for (int l = l0; l < l0 + 128; l++) {
        float x3 = xb[(size_t)l * E2];
        float v  = fmaf(w0,x0, fmaf(w1,x1, fmaf(w2,x2, fmaf(w3,x3, cb))));
        float s  = 1.f / (1.f + __expf(-v));
        ob[(size_t)l * DINNER] = v * s;
        x0 = x1; x1 = x2; x2 = x3;
    }
}

// conv_state[b][d][k] = x[b, d, L-4+k] (pre-conv)
__global__ void conv_state_kernel(float* __restrict__ out)
{
    int idx = blockIdx.x * 256 + threadIdx.x;          // 0..32767
    int b = idx >> 14;
    int r = idx & 16383;
    int d = r >> 2;
    int k = r & 3;
    out[idx] = g_xz[((size_t)(b*LSEQ + (LSEQ - KCONV) + k)) * E2 + d];
}

// ---------------------------------------------------------------------------
// Chunked linear scan.  Per (b, d, chunk) thread: 16 states in registers.
// ---------------------------------------------------------------------------
__global__ void scan_phase1(const float* __restrict__ A_log)
{
    const int d = blockIdx.x * 256 + threadIdx.x;
    const int c = blockIdx.y, b = blockIdx.z;

    float a[DSTATE];
    #pragma unroll
    for (int n = 0; n < DSTATE; n++) a[n] = -__expf(A_log[d*DSTATE + n]);

    float s[DSTATE], ap[DSTATE];
    #pragma unroll
    for (int n = 0; n < DSTATE; n++) { s[n] = 0.f; ap[n] = 1.f; }

    const int mbase = b * LSEQ + c * CLEN;
    for (int t = 0; t < CLEN; t++) {
        const int m = mbase + t;
        const float dt = g_delta[(size_t)m * DINNER + d];
        const float u  = g_xc  [(size_t)m * DINNER + d];
        const float du = dt * u;
        const float* bp = g_xdbl + (size_t)m * XDBL_C + DTRANK;
        #pragma unroll
        for (int n = 0; n < DSTATE; n++) {
            float e = __expf(dt * a[n]);
            s[n]  = fmaf(e, s[n], du * __ldg(bp + n));
            ap[n] *= e;
        }
    }
    const size_t base = ((size_t)(b*NCHUNK + c) * DSTATE) * DINNER + d;
    #pragma unroll
    for (int n = 0; n < DSTATE; n++) {
        g_cA[base + (size_t)n * DINNER] = ap[n];
        g_cS[base + (size_t)n * DINNER] = s[n];
    }
}

__global__ void scan_phase2(float* __restrict__ last_state)
{
    const int d = blockIdx.x * 256 + threadIdx.x;
    const int n = blockIdx.y, b = blockIdx.z;
    float s = 0.f;
    #pragma unroll
    for (int c = 0; c < NCHUNK; c++) {
        const size_t off = ((size_t)(b*NCHUNK + c) * DSTATE + n) * DINNER + d;
        g_sini[off] = s;
        s = fmaf(g_cA[off], s, g_cS[off]);
    }
    last_state[((size_t)b * DINNER + d) * DSTATE + n] = s;
}

__global__ void scan_phase3(const float* __restrict__ A_log,
                            const float* __restrict__ Dvec)
{
    const int d = blockIdx.x * 256 + threadIdx.x;
    const int c = blockIdx.y, b = blockIdx.z;

    float a[DSTATE];
    #pragma unroll
    for (int n = 0; n < DSTATE; n++) a[n] = -__expf(A_log[d*DSTATE + n]);

    float s[DSTATE];
    const size_t base = ((size_t)(b*NCHUNK + c) * DSTATE) * DINNER + d;
    #pragma unroll
    for (int n = 0; n < DSTATE; n++) s[n] = g_sini[base + (size_t)n * DINNER];

    const float Dd = Dvec[d];
    const int mbase = b * LSEQ + c * CLEN;
    for (int t = 0; t < CLEN; t++) {
        const int m = mbase + t;
        const float dt = g_delta[(size_t)m * DINNER + d];
        const float u  = g_xc  [(size_t)m * DINNER + d];
        const float z  = g_xz  [(size_t)m * E2 + DINNER + d];
        const float du = dt * u;
        const float* bp = g_xdbl + (size_t)m * XDBL_C + DTRANK;
        const float* cp = bp + DSTATE;
        float yv = 0.f;
        #pragma unroll
        for (int n = 0; n < DSTATE; n++) {
            float e = __expf(dt * a[n]);
            s[n] = fmaf(e, s[n], du * __ldg(bp + n));
            yv   = fmaf(s[n], __ldg(cp + n), yv);
        }
        yv = fmaf(Dd, u, yv);
        float sig = 1.f / (1.f + __expf(-z));
        g_y[(size_t)m * DINNER + d] = yv * z * sig;
    }
}

// ---------------------------------------------------------------------------
extern "C" void kernel_launch(void* const* d_in, const int* in_sizes, int n_in,
                              void* d_out, int out_size)
{
    const float* hs     = (const float*)d_in[0];
    const float* W_in   = (const float*)d_in[1];
    const float* conv_w = (const float*)d_in[2];
    const float* conv_b = (const float*)d_in[3];
    const float* W_x    = (const float*)d_in[4];
    const float* W_dt   = (const float*)d_in[5];
    const float* b_dt   = (const float*)d_in[6];
    const float* A_log  = (const float*)d_in[7];
    const float* Dv     = (const float*)d_in[8];
    const float* W_out  = (const float*)d_in[9];
    const float* b_out  = (const float*)d_in[10];

    float* out        = (float*)d_out;                              // (B, L, D_MODEL)
    float* conv_state = out + (size_t)BATCH * LSEQ * DMODEL;        // (B, D_INNER, K)
    float* last_state = conv_state + (size_t)BATCH * DINNER * KCONV;// (B, D_INNER, D_STATE)

    float *p_xz, *p_xc, *p_xdbl, *p_delta, *p_y;
    cudaGetSymbolAddress((void**)&p_xz,    g_xz);
    cudaGetSymbolAddress((void**)&p_xc,    g_xc);
    cudaGetSymbolAddress((void**)&p_xdbl,  g_xdbl);
    cudaGetSymbolAddress((void**)&p_delta, g_delta);
    cudaGetSymbolAddress((void**)&p_y,     g_y);

    // 1) xz_t[m][e] = hs[m,:] . W_in[e,:]
    gemm_nt<0><<<dim3(E2/128, MROWS/128), 256>>>(
        MROWS, E2, DMODEL, hs, DMODEL, W_in, DMODEL, p_xz, E2, nullptr);

    // 2) depthwise conv + SiLU; conv_state extraction
    conv_silu_kernel<<<dim3(DINNER/256, LSEQ/128, BATCH), 256>>>(conv_w, conv_b);
    conv_state_kernel<<<dim3((BATCH*DINNER*KCONV)/256), 256>>>(conv_state);

    // 3) x_dbl[m][e] = xc_t[m,:] . W_x[e,:]   (N=160, guarded)
    gemm_nt<0><<<dim3((XDBL_C + 127)/128, MROWS/128), 256>>>(
        MROWS, XDBL_C, DINNER, p_xc, DINNER, W_x, DINNER, p_xdbl, XDBL_C, nullptr);

    // 4) delta_t[m][d] = softplus(dt[m,:] . W_dt[d,:] + b_dt[d])
    gemm_nt<1><<<dim3(DINNER/128, MROWS/128), 256>>>(
        MROWS, DINNER, DTRANK, p_xdbl, XDBL_C, W_dt, DTRANK, p_delta, DINNER, b_dt);

    // 5) chunked selective scan (+ gating epilogue), emits last_state
    scan_phase1<<<dim3(DINNER/256, NCHUNK, BATCH), 256>>>(A_log);
    scan_phase2<<<dim3(DINNER/256, DSTATE, BATCH), 256>>>(last_state);
    scan_phase3<<<dim3(DINNER/256, NCHUNK, BATCH), 256>>>(A_log, Dv);

    // 6) out[m][e] = y_t[m,:] . W_out[e,:] + b_out[e]
    gemm_nt<2><<<dim3(DMODEL/128, MROWS/128), 256>>>(
        MROWS, DMODEL, DINNER, p_y, DINNER, W_out, DINNER, out, DMODEL, b_out);
}

// round 3
// speedup vs baseline: 1.5570x; 1.5570x over previous
#include <cuda_runtime.h>
#include <math.h>
#include <stdint.h>

#define BATCH   2
#define LSEQ    1024
#define DMODEL  2048
#define DINNER  4096
#define DSTATE  16
#define DTRANK  128
#define KCONV   4
#define MROWS   (BATCH*LSEQ)          // 2048
#define E2      (2*DINNER)            // 8192
#define XDBL_C  (DTRANK + 2*DSTATE)   // 160
#define NCHUNK  16
#define CLEN    (LSEQ/NCHUNK)         // 64
#define KSPLIT  8

// -------- scratch (static device globals; no allocation anywhere) ----------
__device__ __align__(16) float g_xz   [(size_t)MROWS * E2];
__device__ __align__(16) float g_xc   [(size_t)MROWS * DINNER];
__device__ __align__(16) float g_xdbl [(size_t)MROWS * XDBL_C];
__device__ __align__(16) float g_delta[(size_t)MROWS * DINNER];
__device__ __align__(16) float g_y    [(size_t)MROWS * DINNER];
__device__ __align__(16) float g_cA   [(size_t)BATCH*NCHUNK*DSTATE*DINNER];
__device__ __align__(16) float g_cS   [(size_t)BATCH*NCHUNK*DSTATE*DINNER];
__device__ __align__(16) float g_sini [(size_t)BATCH*NCHUNK*DSTATE*DINNER];
__device__ __align__(16) float g_part [(size_t)KSPLIT * MROWS * XDBL_C];

// ======================= helpers ============================================
__device__ __forceinline__ float t32(float x) {      // round-to-nearest tf32
    uint32_t u;
    asm("cvt.rna.tf32.f32 %0, %1;" : "=r"(u) : "f"(x));
    return __uint_as_float(u);
}
// swizzled float index within a 128x16 plane (conflict-free stores & frag loads)
__device__ __forceinline__ int swz(int row, int k) {
    return row * 16 + ((((k >> 2) ^ ((row >> 1) & 3)) << 2) | (k & 3));
}
__device__ __forceinline__ void mma8(float* c, const uint32_t* a, const uint32_t* b) {
    asm volatile(
        "mma.sync.aligned.m16n8k8.row.col.f32.tf32.tf32.f32 "
        "{%0,%1,%2,%3}, {%4,%5,%6,%7}, {%8,%9}, {%0,%1,%2,%3};"
        : "+f"(c[0]), "+f"(c[1]), "+f"(c[2]), "+f"(c[3])
        : "r"(a[0]), "r"(a[1]), "r"(a[2]), "r"(a[3]), "r"(b[0]), "r"(b[1]));
}

// ============================================================================
// tf32 3-product NT GEMM: C[i,j] = sum_k A[i,k]*B[j,k] (+ epilogue)
// 128x128 CTA tile, BK=16, 256 threads, warp tile 64x32, double-buffered smem.
// EPI: 0 none, 1 softplus(v+bias[j]), 2 v+bias[j]
// nsplit>1: blockIdx.z handles K-range, writes partial slab z (EPI must be 0).
// Requires M%128==0, K%(16*nsplit)==0. N ragged ok.
// ============================================================================
#define GSMEM (2 * 8192 * 4)   // 2 stages * 8192 floats

template<int EPI>
__global__ void __launch_bounds__(256, 1) mma_gemm(
    int M, int N, int K,
    const float* __restrict__ A, int lda,
    const float* __restrict__ B, int ldb,
    float* __restrict__ C, int ldc,
    const float* __restrict__ bias, int nsplit)
{
    extern __shared__ float smf[];
    const int tid  = threadIdx.x;
    const int lane = tid & 31, wid = tid >> 5;
    const int wm = wid >> 2, wn = wid & 3;           // warp grid 2(m) x 4(n)
    const int g  = lane >> 2, tg = lane & 3;
    const int row0 = blockIdx.y * 128, col0 = blockIdx.x * 128;

    const int kper = K / nsplit;
    const int kbeg = blockIdx.z * kper;
    if (nsplit > 1) C += (size_t)blockIdx.z * M * ldc;
    const int nch = kper / 16;

    float acc[4][4][4];
    #pragma unroll
    for (int i = 0; i < 4; i++)
        #pragma unroll
        for (int j = 0; j < 4; j++)
            #pragma unroll
            for (int q = 0; q < 4; q++) acc[i][j][q] = 0.f;

    // gmem load geometry: thread covers rows rowL & rowL+64, float4 at k=kq*4
    const int rowL = tid >> 2, kq = tid & 3;
    const float* Ap = A + (size_t)(row0 + rowL) * lda + kbeg + kq * 4;
    const float* Bp = B + (size_t)(col0 + rowL) * ldb + kbeg + kq * 4;
    const bool bOk0 = (col0 + rowL)      < N;
    const bool bOk1 = (col0 + rowL + 64) < N;

    const int so0 = rowL * 16        + ((kq ^ ((rowL >> 1) & 3)) << 2);
    const int so1 = (rowL + 64) * 16 + ((kq ^ (((rowL + 64) >> 1) & 3)) << 2);

    float4 pa[2], pb[2];
    pa[0] = __ldg((const float4*)Ap);
    pa[1] = __ldg((const float4*)(Ap + (size_t)64 * lda));
    pb[0] = bOk0 ? __ldg((const float4*)Bp) : make_float4(0.f,0.f,0.f,0.f);
    pb[1] = bOk1 ? __ldg((const float4*)(Bp + (size_t)64 * ldb)) : make_float4(0.f,0.f,0.f,0.f);

    for (int kc = 0; kc < nch; kc++) {
        const int s = kc & 1;
        float* Ah = smf + s * 8192;
        float* Al = Ah + 2048;
        float* Bh = Ah + 4096;
        float* Bl = Ah + 6144;

        // split + store current chunk
        #pragma unroll
        for (int i = 0; i < 2; i++) {
            const int so = i ? so1 : so0;
            float4 x = pa[i];
            float4 h, l;
            h.x = t32(x.x); l.x = t32(x.x - h.x);
            h.y = t32(x.y); l.y = t32(x.y - h.y);
            h.z = t32(x.z); l.z = t32(x.z - h.z);
            h.w = t32(x.w); l.w = t32(x.w - h.w);
            *(float4*)(Ah + so) = h;
            *(float4*)(Al + so) = l;
            x = pb[i];
            h.x = t32(x.x); l.x = t32(x.x - h.x);
            h.y = t32(x.y); l.y = t32(x.y - h.y);
            h.z = t32(x.z); l.z = t32(x.z - h.z);
            h.w = t32(x.w); l.w = t32(x.w - h.w);
            *(float4*)(Bh + so) = h;
            *(float4*)(Bl + so) = l;
        }
        // prefetch next chunk
        if (kc + 1 < nch) {
            const float* Ap2 = Ap + (kc + 1) * 16;
            const float* Bp2 = Bp + (kc + 1) * 16;
            pa[0] = __ldg((const float4*)Ap2);
            pa[1] = __ldg((const float4*)(Ap2 + (size_t)64 * lda));
            pb[0] = bOk0 ? __ldg((const float4*)Bp2) : make_float4(0.f,0.f,0.f,0.f);
            pb[1] = bOk1 ? __ldg((const float4*)(Bp2 + (size_t)64 * ldb)) : make_float4(0.f,0.f,0.f,0.f);
        }
        __syncthreads();

        const uint32_t* Ahu = (const uint32_t*)Ah;
        const uint32_t* Alu = (const uint32_t*)Al;
        const uint32_t* Bhu = (const uint32_t*)Bh;
        const uint32_t* Blu = (const uint32_t*)Bl;

        #pragma unroll
        for (int ks = 0; ks < 2; ks++) {
            const int k0 = ks * 8 + tg;
            uint32_t bh[4][2], bl[4][2];
            #pragma unroll
            for (int nt = 0; nt < 4; nt++) {
                const int rn = wn * 32 + nt * 8 + g;
                bh[nt][0] = Bhu[swz(rn, k0)];
                bh[nt][1] = Bhu[swz(rn, k0 + 4)];
                bl[nt][0] = Blu[swz(rn, k0)];
                bl[nt][1] = Blu[swz(rn, k0 + 4)];
            }
            #pragma unroll
            for (int mt = 0; mt < 4; mt++) {
                const int rm = wm * 64 + mt * 16 + g;
                uint32_t ah[4], al[4];
                ah[0] = Ahu[swz(rm,     k0)];
                ah[1] = Ahu[swz(rm + 8, k0)];
                ah[2] = Ahu[swz(rm,     k0 + 4)];
                ah[3] = Ahu[swz(rm + 8, k0 + 4)];
                al[0] = Alu[swz(rm,     k0)];
                al[1] = Alu[swz(rm + 8, k0)];
                al[2] = Alu[swz(rm,     k0 + 4)];
                al[3] = Alu[swz(rm + 8, k0 + 4)];
                #pragma unroll
                for (int nt = 0; nt < 4; nt++) {
                    mma8(acc[mt][nt], ah, bh[nt]);
                    mma8(acc[mt][nt], ah, bl[nt]);
                    mma8(acc[mt][nt], al, bh[nt]);
                }
            }
        }
        __syncthreads();
    }

    // epilogue: c0,c1 at (r, c..c+1), c2,c3 at (r+8, c..c+1)
    #pragma unroll
    for (int mt = 0; mt < 4; mt++) {
        const int r = row0 + wm * 64 + mt * 16 + g;
        #pragma unroll
        for (int nt = 0; nt < 4; nt++) {
            const int c = col0 + wn * 32 + nt * 8 + 2 * tg;
            if (c < N) {
                float v0 = acc[mt][nt][0], v1 = acc[mt][nt][1];
                float v2 = acc[mt][nt][2], v3 = acc[mt][nt][3];
                if (EPI == 1) {
                    v0 += bias[c]; v1 += bias[c + 1];
                    v2 += bias[c]; v3 += bias[c + 1];
                    v0 = (v0 > 20.f) ? v0 : log1pf(__expf(v0));
                    v1 = (v1 > 20.f) ? v1 : log1pf(__expf(v1));
                    v2 = (v2 > 20.f) ? v2 : log1pf(__expf(v2));
                    v3 = (v3 > 20.f) ? v3 : log1pf(__expf(v3));
                } else if (EPI == 2) {
                    v0 += bias[c]; v1 += bias[c + 1];
                    v2 += bias[c]; v3 += bias[c + 1];
                }
                *(float2*)&C[(size_t)r * ldc + c]       = make_float2(v0, v1);
                *(float2*)&C[(size_t)(r + 8) * ldc + c] = make_float2(v2, v3);
            }
        }
    }
}

// deterministic split-K reduction: g_xdbl[i] = sum_z g_part[z][i]
__global__ void reduce_splitk(int n)
{
    int i = blockIdx.x * 256 + threadIdx.x;
    if (i < n) {
        float s = 0.f;
        #pragma unroll
        for (int z = 0; z < KSPLIT; z++) s += g_part[(size_t)z * n + i];
        g_xdbl[i] = s;
    }
}

// ---------------------------------------------------------------------------
// Depthwise causal conv (K=4) + SiLU
// ---------------------------------------------------------------------------
__global__ void conv_silu_kernel(const float* __restrict__ conv_w,
                                 const float* __restrict__ conv_b)
{
    const int d  = blockIdx.x * 256 + threadIdx.x;
    const int b  = blockIdx.z;
    const int l0 = blockIdx.y * 128;

    const float w0 = conv_w[d*4+0], w1 = conv_w[d*4+1];
    const float w2 = conv_w[d*4+2], w3 = conv_w[d*4+3];
    const float cb = conv_b[d];

    const float* xb = g_xz + (size_t)b * LSEQ * E2 + d;
    float*       ob = g_xc + (size_t)b * LSEQ * DINNER + d;

    float x0 = (l0 >= 3) ? xb[(size_t)(l0-3) * E2] : 0.f;
    float x1 = (l0 >= 2) ? xb[(size_t)(l0-2) * E2] : 0.f;
    float x2 = (l0 >= 1) ? xb[(size_t)(l0-1) * E2] : 0.f;

    for (int l = l0; l < l0 + 128; l++) {
        float x3 = xb[(size_t)l * E2];
        float v  = fmaf(w0,x0, fmaf(w1,x1, fmaf(w2,x2, fmaf(w3,x3, cb))));
        float s  = 1.f / (1.f + __expf(-v));
        ob[(size_t)l * DINNER] = v * s;
        x0 = x1; x1 = x2; x2 = x3;
    }
}

__global__ void conv_state_kernel(float* __restrict__ out)
{
    int idx = blockIdx.x * 256 + threadIdx.x;
    int b = idx >> 14;
    int r = idx & 16383;
    int d = r >> 2;
    int k = r & 3;
    out[idx] = g_xz[((size_t)(b*LSEQ + (LSEQ - KCONV) + k)) * E2 + d];
}

// ---------------------------------------------------------------------------
// Chunked linear scan
// ---------------------------------------------------------------------------
__global__ void scan_phase1(const float* __restrict__ A_log)
{
    const int d = blockIdx.x * 256 + threadIdx.x;
    const int c = blockIdx.y, b = blockIdx.z;

    float a[DSTATE];
    #pragma unroll
    for (int n = 0; n < DSTATE; n++) a[n] = -__expf(A_log[d*DSTATE + n]);

    float s[DSTATE], ap[DSTATE];
    #pragma unroll
    for (int n = 0; n < DSTATE; n++) { s[n] = 0.f; ap[n] = 1.f; }

    const int mbase = b * LSEQ + c * CLEN;
    for (int t = 0; t < CLEN; t++) {
        const int m = mbase + t;
        const float dt = g_delta[(size_t)m * DINNER + d];
        const float u  = g_xc  [(size_t)m * DINNER + d];
        const float du = dt * u;
        const float* bp = g_xdbl + (size_t)m * XDBL_C + DTRANK;
        #pragma unroll
        for (int n = 0; n < DSTATE; n++) {
            float e = __expf(dt * a[n]);
            s[n]  = fmaf(e, s[n], du * __ldg(bp + n));
            ap[n] *= e;
        }
    }
    const size_t base = ((size_t)(b*NCHUNK + c) * DSTATE) * DINNER + d;
    #pragma unroll
    for (int n = 0; n < DSTATE; n++) {
        g_cA[base + (size_t)n * DINNER] = ap[n];
        g_cS[base + (size_t)n * DINNER] = s[n];
    }
}

__global__ void scan_phase2(float* __restrict__ last_state)
{
    const int d = blockIdx.x * 256 + threadIdx.x;
    const int n = blockIdx.y, b = blockIdx.z;
    float s = 0.f;
    #pragma unroll
    for (int c = 0; c < NCHUNK; c++) {
        const size_t off = ((size_t)(b*NCHUNK + c) * DSTATE + n) * DINNER + d;
        g_sini[off] = s;
        s = fmaf(g_cA[off], s, g_cS[off]);
    }
    last_state[((size_t)b * DINNER + d) * DSTATE + n] = s;
}

__global__ void scan_phase3(const float* __restrict__ A_log,
                            const float* __restrict__ Dvec)
{
    const int d = blockIdx.x * 256 + threadIdx.x;
    const int c = blockIdx.y, b = blockIdx.z;

    float a[DSTATE];
    #pragma unroll
    for (int n = 0; n < DSTATE; n++) a[n] = -__expf(A_log[d*DSTATE + n]);

    float s[DSTATE];
    const size_t base = ((size_t)(b*NCHUNK + c) * DSTATE) * DINNER + d;
    #pragma unroll
    for (int n = 0; n < DSTATE; n++) s[n] = g_sini[base + (size_t)n * DINNER];

    const float Dd = Dvec[d];
    const int mbase = b * LSEQ + c * CLEN;
    for (int t = 0; t < CLEN; t++) {
        const int m = mbase + t;
        const float dt = g_delta[(size_t)m * DINNER + d];
        const float u  = g_xc  [(size_t)m * DINNER + d];
        const float z  = g_xz  [(size_t)m * E2 + DINNER + d];
        const float du = dt * u;
        const float* bp = g_xdbl + (size_t)m * XDBL_C + DTRANK;
        const float* cp = bp + DSTATE;
        float yv = 0.f;
        #pragma unroll
        for (int n = 0; n < DSTATE; n++) {
            float e = __expf(dt * a[n]);
            s[n] = fmaf(e, s[n], du * __ldg(bp + n));
            yv   = fmaf(s[n], __ldg(cp + n), yv);
        }
        yv = fmaf(Dd, u, yv);
        float sig = 1.f / (1.f + __expf(-z));
        g_y[(size_t)m * DINNER + d] = yv * z * sig;
    }
}

// ---------------------------------------------------------------------------
extern "C" void kernel_launch(void* const* d_in, const int* in_sizes, int n_in,
                              void* d_out, int out_size)
{
    const float* hs     = (const float*)d_in[0];
    const float* W_in   = (const float*)d_in[1];
    const float* conv_w = (const float*)d_in[2];
    const float* conv_b = (const float*)d_in[3];
    const float* W_x    = (const float*)d_in[4];
    const float* W_dt   = (const float*)d_in[5];
    const float* b_dt   = (const float*)d_in[6];
    const float* A_log  = (const float*)d_in[7];
    const float* Dv     = (const float*)d_in[8];
    const float* W_out  = (const float*)d_in[9];
    const float* b_out  = (const float*)d_in[10];

    float* out        = (float*)d_out;
    float* conv_state = out + (size_t)BATCH * LSEQ * DMODEL;
    float* last_state = conv_state + (size_t)BATCH * DINNER * KCONV;

    float *p_xz, *p_xc, *p_xdbl, *p_delta, *p_y, *p_part;
    cudaGetSymbolAddress((void**)&p_xz,    g_xz);
    cudaGetSymbolAddress((void**)&p_xc,    g_xc);
    cudaGetSymbolAddress((void**)&p_xdbl,  g_xdbl);
    cudaGetSymbolAddress((void**)&p_delta, g_delta);
    cudaGetSymbolAddress((void**)&p_y,     g_y);
    cudaGetSymbolAddress((void**)&p_part,  g_part);

    cudaFuncSetAttribute(mma_gemm<0>, cudaFuncAttributeMaxDynamicSharedMemorySize, GSMEM);
    cudaFuncSetAttribute(mma_gemm<1>, cudaFuncAttributeMaxDynamicSharedMemorySize, GSMEM);
    cudaFuncSetAttribute(mma_gemm<2>, cudaFuncAttributeMaxDynamicSharedMemorySize, GSMEM);

    // 1) xz[m][e] = hs[m,:] . W_in[e,:]      (2048 x 8192 x 2048)
    mma_gemm<0><<<dim3(E2/128, MROWS/128), 256, GSMEM>>>(
        MROWS, E2, DMODEL, hs, DMODEL, W_in, DMODEL, p_xz, E2, nullptr, 1);

    // 2) depthwise conv + SiLU; conv_state
    conv_silu_kernel<<<dim3(DINNER/256, LSEQ/128, BATCH), 256>>>(conv_w, conv_b);
    conv_state_kernel<<<dim3((BATCH*DINNER*KCONV)/256), 256>>>(conv_state);

    // 3) x_dbl[m][e] = xc[m,:] . W_x[e,:]    (2048 x 160 x 4096) split-K=8
    mma_gemm<0><<<dim3(2, MROWS/128, KSPLIT), 256, GSMEM>>>(
        MROWS, XDBL_C, DINNER, p_xc, DINNER, W_x, DINNER, p_part, XDBL_C, nullptr, KSPLIT);
    reduce_splitk<<<(MROWS*XDBL_C + 255)/256, 256>>>(MROWS * XDBL_C);

    // 4) delta[m][d] = softplus(dt[m,:] . W_dt[d,:] + b_dt[d])   (2048 x 4096 x 128)
    mma_gemm<1><<<dim3(DINNER/128, MROWS/128), 256, GSMEM>>>(
        MROWS, DINNER, DTRANK, p_xdbl, XDBL_C, W_dt, DTRANK, p_delta, DINNER, b_dt, 1);

    // 5) chunked selective scan (+ gating epilogue), emits last_state
    scan_phase1<<<dim3(DINNER/256, NCHUNK, BATCH), 256>>>(A_log);
    scan_phase2<<<dim3(DINNER/256, DSTATE, BATCH), 256>>>(last_state);
    scan_phase3<<<dim3(DINNER/256, NCHUNK, BATCH), 256>>>(A_log, Dv);

    // 6) out[m][e] = y[m,:] . W_out[e,:] + b_out[e]   (2048 x 2048 x 4096)
    mma_gemm<2><<<dim3(DMODEL/128, MROWS/128), 256, GSMEM>>>(
        MROWS, DMODEL, DINNER, p_y, DINNER, W_out, DINNER, out, DMODEL, b_out, 1);
}

// round 4
// speedup vs baseline: 2.9690x; 1.9068x over previous
#include <cuda_runtime.h>
#include <cuda_bf16.h>
#include <math.h>
#include <stdint.h>

#define BATCH   2
#define LSEQ    1024
#define DMODEL  2048
#define DINNER  4096
#define DSTATE  16
#define DTRANK  128
#define KCONV   4
#define MROWS   (BATCH*LSEQ)          // 2048
#define E2      (2*DINNER)            // 8192
#define XDBL_C  (DTRANK + 2*DSTATE)   // 160
#define NCHUNK  16
#define CLEN    (LSEQ/NCHUNK)         // 64
#define KSPLIT  8

// -------- fp32 scratch ------------------------------------------------------
__device__ __align__(16) float g_xz   [(size_t)MROWS * E2];
__device__ __align__(16) float g_xc   [(size_t)MROWS * DINNER];
__device__ __align__(16) float g_xdbl [(size_t)MROWS * XDBL_C];
__device__ __align__(16) float g_delta[(size_t)MROWS * DINNER];
__device__ __align__(16) float g_cA   [(size_t)BATCH*NCHUNK*DSTATE*DINNER];
__device__ __align__(16) float g_cS   [(size_t)BATCH*NCHUNK*DSTATE*DINNER];
__device__ __align__(16) float g_sini [(size_t)BATCH*NCHUNK*DSTATE*DINNER];
__device__ __align__(16) float g_part [(size_t)KSPLIT * MROWS * XDBL_C];

// -------- bf16 hi/lo planes -------------------------------------------------
__device__ __align__(16) __nv_bfloat16 g_hsH [(size_t)MROWS * DMODEL];
__device__ __align__(16) __nv_bfloat16 g_hsL [(size_t)MROWS * DMODEL];
__device__ __align__(16) __nv_bfloat16 g_winH[(size_t)E2 * DMODEL];
__device__ __align__(16) __nv_bfloat16 g_winL[(size_t)E2 * DMODEL];
__device__ __align__(16) __nv_bfloat16 g_xcH [(size_t)MROWS * DINNER];
__device__ __align__(16) __nv_bfloat16 g_xcL [(size_t)MROWS * DINNER];
__device__ __align__(16) __nv_bfloat16 g_wxH [(size_t)XDBL_C * DINNER];
__device__ __align__(16) __nv_bfloat16 g_wxL [(size_t)XDBL_C * DINNER];
__device__ __align__(16) __nv_bfloat16 g_dtH [(size_t)MROWS * DTRANK];
__device__ __align__(16) __nv_bfloat16 g_dtL [(size_t)MROWS * DTRANK];
__device__ __align__(16) __nv_bfloat16 g_wdtH[(size_t)DINNER * DTRANK];
__device__ __align__(16) __nv_bfloat16 g_wdtL[(size_t)DINNER * DTRANK];
__device__ __align__(16) __nv_bfloat16 g_yH  [(size_t)MROWS * DINNER];
__device__ __align__(16) __nv_bfloat16 g_yL  [(size_t)MROWS * DINNER];
__device__ __align__(16) __nv_bfloat16 g_woH [(size_t)DMODEL * DINNER];
__device__ __align__(16) __nv_bfloat16 g_woL [(size_t)DMODEL * DINNER];

// ======================= PTX helpers ========================================
__device__ __forceinline__ uint32_t smem_u32(const void* p) {
    uint32_t a;
    asm("{ .reg .u64 t; cvta.to.shared.u64 t, %1; cvt.u32.u64 %0, t; }"
        : "=r"(a) : "l"(p));
    return a;
}
__device__ __forceinline__ void cpa16(uint32_t dst, const void* src, uint32_t sz) {
    asm volatile("cp.async.cg.shared.global [%0], [%1], 16, %2;"
                 :: "r"(dst), "l"(src), "r"(sz) : "memory");
}
__device__ __forceinline__ void cpa_commit() {
    asm volatile("cp.async.commit_group;" ::: "memory");
}
__device__ __forceinline__ void cpa_wait1() {
    asm volatile("cp.async.wait_group 1;" ::: "memory");
}
__device__ __forceinline__ void ldsm4(uint32_t* r, uint32_t addr) {
    asm volatile("ldmatrix.sync.aligned.m8n8.x4.shared.b16 {%0,%1,%2,%3}, [%4];"
                 : "=r"(r[0]), "=r"(r[1]), "=r"(r[2]), "=r"(r[3]) : "r"(addr));
}
__device__ __forceinline__ void mma16(float* c, const uint32_t* a, const uint32_t* b) {
    asm volatile(
        "mma.sync.aligned.m16n8k16.row.col.f32.bf16.bf16.f32 "
        "{%0,%1,%2,%3}, {%4,%5,%6,%7}, {%8,%9}, {%0,%1,%2,%3};"
        : "+f"(c[0]), "+f"(c[1]), "+f"(c[2]), "+f"(c[3])
        : "r"(a[0]), "r"(a[1]), "r"(a[2]), "r"(a[3]), "r"(b[0]), "r"(b[1]));
}

// ============================================================================
// bf16 3-product NT GEMM over virtual K' = 3K:
//   C[i,j] = sum_k ( AH*BH + AH*BL + AL*BH )[i,j]   ~= fp32 A.B^T
// CTA tile 128x128, BK=32 per chunk, 3-stage cp.async ring, ldmatrix + HMMA.
// EPI: 0 none, 1 softplus(v+bias[j]), 2 v+bias[j]
// nsplit>1: blockIdx.z takes a K-range, writes partial slab z (EPI must be 0).
// Requires M%128==0, K%(32*nsplit)==0. N ragged ok.
// ============================================================================
#define STAGE_BYTES 16384u
#define G_SMEM      (3u * STAGE_BYTES)   // 48 KB

template<int EPI>
__global__ void __launch_bounds__(256, 2) bf_gemm(
    int M, int N, int K,
    const __nv_bfloat16* __restrict__ AH, const __nv_bfloat16* __restrict__ AL, int lda,
    const __nv_bfloat16* __restrict__ BH, const __nv_bfloat16* __restrict__ BL, int ldb,
    float* __restrict__ C, int ldc,
    const float* __restrict__ bias, int nsplit)
{
    extern __shared__ char smem[];
    const uint32_t sbase = smem_u32(smem);
    const int tid = threadIdx.x, lane = tid & 31, wid = tid >> 5;
    const int wm = wid >> 2, wn = wid & 3;           // warp grid 2(m) x 4(n)
    const int g = lane >> 2, tg = lane & 3;
    const int row0 = blockIdx.y * 128, col0 = blockIdx.x * 128;

    const int kper = K / nsplit;
    const int kbeg = blockIdx.z * kper;
    if (nsplit > 1) C += (size_t)blockIdx.z * M * ldc;
    const int nchT = kper / 32;
    const int nch  = 3 * nchT;

    // per-lane ldmatrix address components
    const int aro = (lane & 7) + ((lane >> 3) & 1) * 8;  // A row offset
    const int aco = lane >> 4;                            // A chunk offset
    const int bro = (lane & 7) + ((lane >> 4) << 3);      // B row offset
    const int bco = (lane >> 3) & 1;                      // B chunk offset

    float acc[4][4][4];
    #pragma unroll
    for (int i = 0; i < 4; i++)
        #pragma unroll
        for (int j = 0; j < 4; j++)
            #pragma unroll
            for (int q = 0; q < 4; q++) acc[i][j][q] = 0.f;

    auto issue = [&](int c) {
        if (c < nch) {
            const int t  = (c >= 2 * nchT) ? 2 : ((c >= nchT) ? 1 : 0);
            const int kk = c - t * nchT;
            const int koff = kbeg + kk * 32;
            const __nv_bfloat16* Ap = (t == 2) ? AL : AH;
            const __nv_bfloat16* Bp = (t == 1) ? BL : BH;
            const uint32_t st = sbase + (uint32_t)(c % 3) * STAGE_BYTES;
            #pragma unroll
            for (int i = 0; i < 2; i++) {
                const int idx = tid + i * 256;
                const int row = idx >> 2, ch = idx & 3;
                const uint32_t sw = (uint32_t)(row * 64 + ((ch ^ ((row >> 1) & 3)) << 4));
                cpa16(st + sw, Ap + (size_t)(row0 + row) * lda + koff + ch * 8, 16u);
                const uint32_t szB = ((col0 + row) < N) ? 16u : 0u;
                cpa16(st + 8192u + sw, Bp + (size_t)(col0 + row) * ldb + koff + ch * 8, szB);
            }
        }
        cpa_commit();
    };

    issue(0);
    issue(1);

    for (int c = 0; c < nch; c++) {
        cpa_wait1();
        __syncthreads();
        issue(c + 2);

        const uint32_t sA = sbase + (uint32_t)(c % 3) * STAGE_BYTES;
        const uint32_t sB = sA + 8192u;
        #pragma unroll
        for (int kk = 0; kk < 2; kk++) {
            uint32_t bb[8];
            #pragma unroll
            for (int p = 0; p < 2; p++) {
                const int row = wn * 32 + p * 16 + bro;
                const int ch  = 2 * kk + bco;
                ldsm4(&bb[p * 4],
                      sB + (uint32_t)(row * 64 + ((ch ^ ((row >> 1) & 3)) << 4)));
            }
            #pragma unroll
            for (int mt = 0; mt < 4; mt++) {
                const int row = wm * 64 + mt * 16 + aro;
                const int ch  = 2 * kk + aco;
                uint32_t aa[4];
                ldsm4(aa, sA + (uint32_t)(row * 64 + ((ch ^ ((row >> 1) & 3)) << 4)));
                mma16(acc[mt][0], aa, &bb[0]);
                mma16(acc[mt][1], aa, &bb[2]);
                mma16(acc[mt][2], aa, &bb[4]);
                mma16(acc[mt][3], aa, &bb[6]);
            }
        }
    }

    // epilogue: c0,c1 at (r, c..c+1); c2,c3 at (r+8, c..c+1)
    #pragma unroll
    for (int mt = 0; mt < 4; mt++) {
        const int r = row0 + wm * 64 + mt * 16 + g;
        #pragma unroll
        for (int nt = 0; nt < 4; nt++) {
            const int c2 = col0 + wn * 32 + nt * 8 + 2 * tg;
            if (c2 < N) {
                float v0 = acc[mt][nt][0], v1 = acc[mt][nt][1];
                float v2 = acc[mt][nt][2], v3 = acc[mt][nt][3];
                if (EPI == 1) {
                    v0 += bias[c2]; v1 += bias[c2 + 1];
                    v2 += bias[c2]; v3 += bias[c2 + 1];
                    v0 = (v0 > 20.f) ? v0 : log1pf(__expf(v0));
                    v1 = (v1 > 20.f) ? v1 : log1pf(__expf(v1));
                    v2 = (v2 > 20.f) ? v2 : log1pf(__expf(v2));
                    v3 = (v3 > 20.f) ? v3 : log1pf(__expf(v3));
                } else if (EPI == 2) {
                    v0 += bias[c2]; v1 += bias[c2 + 1];
                    v2 += bias[c2]; v3 += bias[c2 + 1];
                }
                *(float2*)&C[(size_t)r * ldc + c2]       = make_float2(v0, v1);
                *(float2*)&C[(size_t)(r + 8) * ldc + c2] = make_float2(v2, v3);
            }
        }
    }
}

// ---------------------------------------------------------------------------
// hi/lo bf16 split kernels
// ---------------------------------------------------------------------------
__global__ void split_bf16(const float* __restrict__ src,
                           __nv_bfloat16* __restrict__ hi,
                           __nv_bfloat16* __restrict__ lo, int n4)
{
    const int i = blockIdx.x * 256 + threadIdx.x;
    if (i >= n4) return;
    const float4 v = ((const float4*)src)[i];
    __nv_bfloat162 h0, h1, l0, l1;
    h0.x = __float2bfloat16(v.x); l0.x = __float2bfloat16(v.x - __bfloat162float(h0.x));
    h0.y = __float2bfloat16(v.y); l0.y = __float2bfloat16(v.y - __bfloat162float(h0.y));
    h1.x = __float2bfloat16(v.z); l1.x = __float2bfloat16(v.z - __bfloat162float(h1.x));
    h1.y = __float2bfloat16(v.w); l1.y = __float2bfloat16(v.w - __bfloat162float(h1.y));
    ((__nv_bfloat162*)hi)[2*i]   = h0; ((__nv_bfloat162*)hi)[2*i+1] = h1;
    ((__nv_bfloat162*)lo)[2*i]   = l0; ((__nv_bfloat162*)lo)[2*i+1] = l1;
}

// split dt = g_xdbl[:, 0:128] (ld 160) -> compact 2048x128 planes
__global__ void split_dt_kernel()
{
    const int i = blockIdx.x * 256 + threadIdx.x;   // 2048*32 float4s
    if (i >= MROWS * (DTRANK/4)) return;
    const int row = i >> 5, c4 = i & 31;
    const float4 v = *(const float4*)(g_xdbl + (size_t)row * XDBL_C + c4 * 4);
    __nv_bfloat162 h0, h1, l0, l1;
    h0.x = __float2bfloat16(v.x); l0.x = __float2bfloat16(v.x - __bfloat162float(h0.x));
    h0.y = __float2bfloat16(v.y); l0.y = __float2bfloat16(v.y - __bfloat162float(h0.y));
    h1.x = __float2bfloat16(v.z); l1.x = __float2bfloat16(v.z - __bfloat162float(h1.x));
    h1.y = __float2bfloat16(v.w); l1.y = __float2bfloat16(v.w - __bfloat162float(h1.y));
    const size_t o = (size_t)row * DTRANK + c4 * 4;
    *(__nv_bfloat162*)(g_dtH + o)     = h0; *(__nv_bfloat162*)(g_dtH + o + 2) = h1;
    *(__nv_bfloat162*)(g_dtL + o)     = l0; *(__nv_bfloat162*)(g_dtL + o + 2) = l1;
}

// deterministic split-K reduction
__global__ void reduce_splitk(int n)
{
    const int i = blockIdx.x * 256 + threadIdx.x;
    if (i < n) {
        float s = 0.f;
        #pragma unroll
        for (int z = 0; z < KSPLIT; z++) s += g_part[(size_t)z * n + i];
        g_xdbl[i] = s;
    }
}

// ---------------------------------------------------------------------------
// Depthwise causal conv (K=4) + SiLU, fused xc hi/lo split
// ---------------------------------------------------------------------------
__global__ void conv_silu_kernel(const float* __restrict__ conv_w,
                                 const float* __restrict__ conv_b)
{
    const int d  = blockIdx.x * 256 + threadIdx.x;
    const int b  = blockIdx.z;
    const int l0 = blockIdx.y * 128;

    const float w0 = conv_w[d*4+0], w1 = conv_w[d*4+1];
    const float w2 = conv_w[d*4+2], w3 = conv_w[d*4+3];
    const float cb = conv_b[d];

    const float* xb = g_xz + (size_t)b * LSEQ * E2 + d;
    const size_t ob = (size_t)b * LSEQ * DINNER + d;

    float x0 = (l0 >= 3) ? xb[(size_t)(l0-3) * E2] : 0.f;
    float x1 = (l0 >= 2) ? xb[(size_t)(l0-2) * E2] : 0.f;
    float x2 = (l0 >= 1) ? xb[(size_t)(l0-1) * E2] : 0.f;

    for (int l = l0; l < l0 + 128; l++) {
        float x3 = xb[(size_t)l * E2];
        float v  = fmaf(w0,x0, fmaf(w1,x1, fmaf(w2,x2, fmaf(w3,x3, cb))));
        float s  = 1.f / (1.f + __expf(-v));
        float o  = v * s;
        const size_t off = ob + (size_t)l * DINNER;
        g_xc[off] = o;
        __nv_bfloat16 h = __float2bfloat16(o);
        g_xcH[off] = h;
        g_xcL[off] = __float2bfloat16(o - __bfloat162float(h));
        x0 = x1; x1 = x2; x2 = x3;
    }
}

__global__ void conv_state_kernel(float* __restrict__ out)
{
    const int idx = blockIdx.x * 256 + threadIdx.x;
    const int b = idx >> 14;
    const int r = idx & 16383;
    const int d = r >> 2;
    const int k = r & 3;
    out[idx] = g_xz[((size_t)(b*LSEQ + (LSEQ - KCONV) + k)) * E2 + d];
}

// ---------------------------------------------------------------------------
// Chunked linear scan
// ---------------------------------------------------------------------------
__global__ void scan_phase1(const float* __restrict__ A_log)
{
    const int d = blockIdx.x * 256 + threadIdx.x;
    const int c = blockIdx.y, b = blockIdx.z;

    float a[DSTATE];
    #pragma unroll
    for (int n = 0; n < DSTATE; n++) a[n] = -__expf(A_log[d*DSTATE + n]);

    float s[DSTATE], ap[DSTATE];
    #pragma unroll
    for (int n = 0; n < DSTATE; n++) { s[n] = 0.f; ap[n] = 1.f; }

    const int mbase = b * LSEQ + c * CLEN;
    for (int t = 0; t < CLEN; t++) {
        const int m = mbase + t;
        const float dt = g_delta[(size_t)m * DINNER + d];
        const float u  = g_xc  [(size_t)m * DINNER + d];
        const float du = dt * u;
        const float* bp = g_xdbl + (size_t)m * XDBL_C + DTRANK;
        #pragma unroll
        for (int n = 0; n < DSTATE; n++) {
            float e = __expf(dt * a[n]);
            s[n]  = fmaf(e, s[n], du * __ldg(bp + n));
            ap[n] *= e;
        }
    }
    const size_t base = ((size_t)(b*NCHUNK + c) * DSTATE) * DINNER + d;
    #pragma unroll
    for (int n = 0; n < DSTATE; n++) {
        g_cA[base + (size_t)n * DINNER] = ap[n];
        g_cS[base + (size_t)n * DINNER] = s[n];
    }
}

__global__ void scan_phase2(float* __restrict__ last_state)
{
    const int d = blockIdx.x * 256 + threadIdx.x;
    const int n = blockIdx.y, b = blockIdx.z;
    float s = 0.f;
    #pragma unroll
    for (int c = 0; c < NCHUNK; c++) {
        const size_t off = ((size_t)(b*NCHUNK + c) * DSTATE + n) * DINNER + d;
        g_sini[off] = s;
        s = fmaf(g_cA[off], s, g_cS[off]);
    }
    last_state[((size_t)b * DINNER + d) * DSTATE + n] = s;
}

__global__ void scan_phase3(const float* __restrict__ A_log,
                            const float* __restrict__ Dvec)
{
    const int d = blockIdx.x * 256 + threadIdx.x;
    const int c = blockIdx.y, b = blockIdx.z;

    float a[DSTATE];
    #pragma unroll
    for (int n = 0; n < DSTATE; n++) a[n] = -__expf(A_log[d*DSTATE + n]);

    float s[DSTATE];
    const size_t base = ((size_t)(b*NCHUNK + c) * DSTATE) * DINNER + d;
    #pragma unroll
    for (int n = 0; n < DSTATE; n++) s[n] = g_sini[base + (size_t)n * DINNER];

    const float Dd = Dvec[d];
    const int mbase = b * LSEQ + c * CLEN;
    for (int t = 0; t < CLEN; t++) {
        const int m = mbase + t;
        const float dt = g_delta[(size_t)m * DINNER + d];
        const float u  = g_xc  [(size_t)m * DINNER + d];
        const float z  = g_xz  [(size_t)m * E2 + DINNER + d];
        const float du = dt * u;
        const float* bp = g_xdbl + (size_t)m * XDBL_C + DTRANK;
        const float* cp = bp + DSTATE;
        float yv = 0.f;
        #pragma unroll
        for (int n = 0; n < DSTATE; n++) {
            float e = __expf(dt * a[n]);
            s[n] = fmaf(e, s[n], du * __ldg(bp + n));
            yv   = fmaf(s[n], __ldg(cp + n), yv);
        }
        yv = fmaf(Dd, u, yv);
        const float sig = 1.f / (1.f + __expf(-z));
        const float yo  = yv * z * sig;
        const size_t off = (size_t)m * DINNER + d;
        __nv_bfloat16 h = __float2bfloat16(yo);
        g_yH[off] = h;
        g_yL[off] = __float2bfloat16(yo - __bfloat162float(h));
    }
}

// ---------------------------------------------------------------------------
extern "C" void kernel_launch(void* const* d_in, const int* in_sizes, int n_in,
                              void* d_out, int out_size)
{
    const float* hs     = (const float*)d_in[0];
    const float* W_in   = (const float*)d_in[1];
    const float* conv_w = (const float*)d_in[2];
    const float* conv_b = (const float*)d_in[3];
    const float* W_x    = (const float*)d_in[4];
    const float* W_dt   = (const float*)d_in[5];
    const float* b_dt   = (const float*)d_in[6];
    const float* A_log  = (const float*)d_in[7];
    const float* Dv     = (const float*)d_in[8];
    const float* W_out  = (const float*)d_in[9];
    const float* b_out  = (const float*)d_in[10];

    float* out        = (float*)d_out;
    float* conv_state = out + (size_t)BATCH * LSEQ * DMODEL;
    float* last_state = conv_state + (size_t)BATCH * DINNER * KCONV;

    float *p_xz, *p_xdbl, *p_delta, *p_part;
    cudaGetSymbolAddress((void**)&p_xz,    g_xz);
    cudaGetSymbolAddress((void**)&p_xdbl,  g_xdbl);
    cudaGetSymbolAddress((void**)&p_delta, g_delta);
    cudaGetSymbolAddress((void**)&p_part,  g_part);

    __nv_bfloat16 *hsH,*hsL,*winH,*winL,*xcH,*xcL,*wxH,*wxL,*dtH,*dtL,*wdtH,*wdtL,*yH,*yL,*woH,*woL;
    cudaGetSymbolAddress((void**)&hsH, g_hsH);   cudaGetSymbolAddress((void**)&hsL, g_hsL);
    cudaGetSymbolAddress((void**)&winH, g_winH); cudaGetSymbolAddress((void**)&winL, g_winL);
    cudaGetSymbolAddress((void**)&xcH, g_xcH);   cudaGetSymbolAddress((void**)&xcL, g_xcL);
    cudaGetSymbolAddress((void**)&wxH, g_wxH);   cudaGetSymbolAddress((void**)&wxL, g_wxL);
    cudaGetSymbolAddress((void**)&dtH, g_dtH);   cudaGetSymbolAddress((void**)&dtL, g_dtL);
    cudaGetSymbolAddress((void**)&wdtH, g_wdtH); cudaGetSymbolAddress((void**)&wdtL, g_wdtL);
    cudaGetSymbolAddress((void**)&yH, g_yH);     cudaGetSymbolAddress((void**)&yL, g_yL);
    cudaGetSymbolAddress((void**)&woH, g_woH);   cudaGetSymbolAddress((void**)&woL, g_woL);

    cudaFuncSetAttribute(bf_gemm<0>, cudaFuncAttributeMaxDynamicSharedMemorySize, G_SMEM);
    cudaFuncSetAttribute(bf_gemm<1>, cudaFuncAttributeMaxDynamicSharedMemorySize, G_SMEM);
    cudaFuncSetAttribute(bf_gemm<2>, cudaFuncAttributeMaxDynamicSharedMemorySize, G_SMEM);

    // 0) hi/lo splits of pure inputs
    split_bf16<<<(MROWS*DMODEL/4 + 255)/256, 256>>>(hs,    hsH,  hsL,  MROWS*DMODEL/4);
    split_bf16<<<(E2*DMODEL/4   + 255)/256, 256>>>(W_in,  winH, winL, E2*DMODEL/4);
    split_bf16<<<(XDBL_C*DINNER/4 + 255)/256, 256>>>(W_x,  wxH,  wxL,  XDBL_C*DINNER/4);
    split_bf16<<<(DINNER*DTRANK/4 + 255)/256, 256>>>(W_dt, wdtH, wdtL, DINNER*DTRANK/4);
    split_bf16<<<(DMODEL*DINNER/4 + 255)/256, 256>>>(W_out, woH, woL,  DMODEL*DINNER/4);

    // 1) xz[m][e] = hs[m,:] . W_in[e,:]      (2048 x 8192 x 2048)
    bf_gemm<0><<<dim3(E2/128, MROWS/128), 256, G_SMEM>>>(
        MROWS, E2, DMODEL, hsH, hsL, DMODEL, winH, winL, DMODEL, p_xz, E2, nullptr, 1);

    // 2) depthwise conv + SiLU (fused xc split); conv_state
    conv_silu_kernel<<<dim3(DINNER/256, LSEQ/128, BATCH), 256>>>(conv_w, conv_b);
    conv_state_kernel<<<dim3((BATCH*DINNER*KCONV)/256), 256>>>(conv_state);

    // 3) x_dbl[m][e] = xc[m,:] . W_x[e,:]    (2048 x 160 x 4096) split-K=8
    bf_gemm<0><<<dim3(2, MROWS/128, KSPLIT), 256, G_SMEM>>>(
        MROWS, XDBL_C, DINNER, xcH, xcL, DINNER, wxH, wxL, DINNER, p_part, XDBL_C, nullptr, KSPLIT);
    reduce_splitk<<<(MROWS*XDBL_C + 255)/256, 256>>>(MROWS * XDBL_C);
    split_dt_kernel<<<(MROWS*(DTRANK/4) + 255)/256, 256>>>();

    // 4) delta[m][d] = softplus(dt[m,:] . W_dt[d,:] + b_dt[d])   (2048 x 4096 x 128)
    bf_gemm<1><<<dim3(DINNER/128, MROWS/128), 256, G_SMEM>>>(
        MROWS, DINNER, DTRANK, dtH, dtL, DTRANK, wdtH, wdtL, DTRANK, p_delta, DINNER, b_dt, 1);

    // 5) chunked selective scan (+ gating, fused y split), emits last_state
    scan_phase1<<<dim3(DINNER/256, NCHUNK, BATCH), 256>>>(A_log);
    scan_phase2<<<dim3(DINNER/256, DSTATE, BATCH), 256>>>(last_state);
    scan_phase3<<<dim3(DINNER/256, NCHUNK, BATCH), 256>>>(A_log, Dv);

    // 6) out[m][e] = y[m,:] . W_out[e,:] + b_out[e]   (2048 x 2048 x 4096)
    bf_gemm<2><<<dim3(DMODEL/128, MROWS/128), 256, G_SMEM>>>(
        MROWS, DMODEL, DINNER, yH, yL, DINNER, woH, woL, DINNER, out, DMODEL, b_out, 1);
}

// round 5
// speedup vs baseline: 3.2150x; 1.0829x over previous
#include <cuda_runtime.h>
#include <cuda_bf16.h>
#include <math.h>
#include <stdint.h>

#define BATCH   2
#define LSEQ    1024
#define DMODEL  2048
#define DINNER  4096
#define DSTATE  16
#define DTRANK  128
#define KCONV   4
#define MROWS   (BATCH*LSEQ)          // 2048
#define E2      (2*DINNER)            // 8192
#define XDBL_C  (DTRANK + 2*DSTATE)   // 160
#define NCHUNK  16
#define CLEN    (LSEQ/NCHUNK)         // 64
#define KSPLIT  8

// -------- fp32 scratch ------------------------------------------------------
__device__ __align__(16) float g_xz   [(size_t)MROWS * E2];
__device__ __align__(16) float g_xc   [(size_t)MROWS * DINNER];
__device__ __align__(16) float g_xdbl [(size_t)MROWS * XDBL_C];
__device__ __align__(16) float g_delta[(size_t)MROWS * DINNER];
__device__ __align__(16) float g_cA   [(size_t)BATCH*NCHUNK*DSTATE*DINNER];
__device__ __align__(16) float g_cS   [(size_t)BATCH*NCHUNK*DSTATE*DINNER];
__device__ __align__(16) float g_sini [(size_t)BATCH*NCHUNK*DSTATE*DINNER];
__device__ __align__(16) float g_part [(size_t)KSPLIT * MROWS * XDBL_C];

// -------- bf16 hi/lo planes -------------------------------------------------
__device__ __align__(16) __nv_bfloat16 g_hsH [(size_t)MROWS * DMODEL];
__device__ __align__(16) __nv_bfloat16 g_hsL [(size_t)MROWS * DMODEL];
__device__ __align__(16) __nv_bfloat16 g_winH[(size_t)E2 * DMODEL];
__device__ __align__(16) __nv_bfloat16 g_winL[(size_t)E2 * DMODEL];
__device__ __align__(16) __nv_bfloat16 g_xcH [(size_t)MROWS * DINNER];
__device__ __align__(16) __nv_bfloat16 g_xcL [(size_t)MROWS * DINNER];
__device__ __align__(16) __nv_bfloat16 g_wxH [(size_t)XDBL_C * DINNER];
__device__ __align__(16) __nv_bfloat16 g_wxL [(size_t)XDBL_C * DINNER];
__device__ __align__(16) __nv_bfloat16 g_dtH [(size_t)MROWS * DTRANK];
__device__ __align__(16) __nv_bfloat16 g_dtL [(size_t)MROWS * DTRANK];
__device__ __align__(16) __nv_bfloat16 g_wdtH[(size_t)DINNER * DTRANK];
__device__ __align__(16) __nv_bfloat16 g_wdtL[(size_t)DINNER * DTRANK];
__device__ __align__(16) __nv_bfloat16 g_yH  [(size_t)MROWS * DINNER];
__device__ __align__(16) __nv_bfloat16 g_yL  [(size_t)MROWS * DINNER];
__device__ __align__(16) __nv_bfloat16 g_woH [(size_t)DMODEL * DINNER];
__device__ __align__(16) __nv_bfloat16 g_woL [(size_t)DMODEL * DINNER];

// ======================= PTX helpers ========================================
__device__ __forceinline__ uint32_t smem_u32(const void* p) {
    uint32_t a;
    asm("{ .reg .u64 t; cvta.to.shared.u64 t, %1; cvt.u32.u64 %0, t; }"
        : "=r"(a) : "l"(p));
    return a;
}
__device__ __forceinline__ void cpa16(uint32_t dst, const void* src, uint32_t sz) {
    asm volatile("cp.async.cg.shared.global [%0], [%1], 16, %2;"
                 :: "r"(dst), "l"(src), "r"(sz) : "memory");
}
__device__ __forceinline__ void cpa_commit() {
    asm volatile("cp.async.commit_group;" ::: "memory");
}
__device__ __forceinline__ void cpa_wait1() {
    asm volatile("cp.async.wait_group 1;" ::: "memory");
}
__device__ __forceinline__ void ldsm4(uint32_t* r, uint32_t addr) {
    asm volatile("ldmatrix.sync.aligned.m8n8.x4.shared.b16 {%0,%1,%2,%3}, [%4];"
                 : "=r"(r[0]), "=r"(r[1]), "=r"(r[2]), "=r"(r[3]) : "r"(addr));
}
__device__ __forceinline__ void mma16(float* c, const uint32_t* a, const uint32_t* b) {
    asm volatile(
        "mma.sync.aligned.m16n8k16.row.col.f32.bf16.bf16.f32 "
        "{%0,%1,%2,%3}, {%4,%5,%6,%7}, {%8,%9}, {%0,%1,%2,%3};"
        : "+f"(c[0]), "+f"(c[1]), "+f"(c[2]), "+f"(c[3])
        : "r"(a[0]), "r"(a[1]), "r"(a[2]), "r"(a[3]), "r"(b[0]), "r"(b[1]));
}
// swizzled byte offset inside an 8 KB plane: 128 rows x 64B
__device__ __forceinline__ uint32_t swf(int row, int ch) {
    return (uint32_t)(row * 64 + ((ch ^ ((row >> 1) & 3)) << 4));
}

// ============================================================================
// bf16 3-product NT GEMM (4-plane chunks):
//   C[i,j] = sum_k ( AH*BH + AH*BL + AL*BH )[i,j]   ~= fp32 A.B^T
// CTA tile 128x128, BK=32; stage holds {AH,AL,BH,BL} (32 KB); 3-stage ring.
// 96 HMMA / warp / chunk. EPI: 0 none, 1 softplus(v+bias), 2 v+bias.
// nsplit>1: blockIdx.z takes a K-range, writes partial slab z (EPI must be 0).
// Requires M%128==0, K%(32*nsplit)==0. N ragged ok.
// ============================================================================
#define STAGE_BYTES 32768u
#define G_SMEM      (3u * STAGE_BYTES)   // 96 KB

template<int EPI>
__global__ void __launch_bounds__(256, 2) bf_gemm(
    int M, int N, int K,
    const __nv_bfloat16* __restrict__ AH, const __nv_bfloat16* __restrict__ AL, int lda,
    const __nv_bfloat16* __restrict__ BH, const __nv_bfloat16* __restrict__ BL, int ldb,
    float* __restrict__ C, int ldc,
    const float* __restrict__ bias, int nsplit)
{
    extern __shared__ char smem[];
    const uint32_t sbase = smem_u32(smem);
    const int tid = threadIdx.x, lane = tid & 31, wid = tid >> 5;
    const int wm = wid >> 2, wn = wid & 3;           // warp grid 2(m) x 4(n)
    const int g = lane >> 2, tg = lane & 3;
    const int row0 = blockIdx.y * 128, col0 = blockIdx.x * 128;

    const int kper = K / nsplit;
    const int kbeg = blockIdx.z * kper;
    if (nsplit > 1) C += (size_t)blockIdx.z * M * ldc;
    const int nch = kper / 32;

    // per-lane ldmatrix address components
    const int aro = (lane & 7) + ((lane >> 3) & 1) * 8;  // A row offset
    const int aco = lane >> 4;                            // A k-chunk offset
    const int bro = (lane & 7) + ((lane >> 4) << 3);      // B row offset
    const int bco = (lane >> 3) & 1;                      // B k-chunk offset

    float acc[4][4][4];
    #pragma unroll
    for (int i = 0; i < 4; i++)
        #pragma unroll
        for (int j = 0; j < 4; j++)
            #pragma unroll
            for (int q = 0; q < 4; q++) acc[i][j][q] = 0.f;

    auto issue = [&](int c) {
        if (c < nch) {
            const int koff = kbeg + c * 32;
            const uint32_t st = sbase + (uint32_t)(c % 3) * STAGE_BYTES;
            #pragma unroll
            for (int i = 0; i < 2; i++) {
                const int idx = tid + i * 256;
                const int row = idx >> 2, ch = idx & 3;
                const uint32_t sw = swf(row, ch);
                const size_t ga = (size_t)(row0 + row) * lda + koff + ch * 8;
                cpa16(st + sw,          AH + ga, 16u);
                cpa16(st + 8192u + sw,  AL + ga, 16u);
                const uint32_t szB = ((col0 + row) < N) ? 16u : 0u;
                const size_t gb = (size_t)(col0 + row) * ldb + koff + ch * 8;
                cpa16(st + 16384u + sw, BH + gb, szB);
                cpa16(st + 24576u + sw, BL + gb, szB);
            }
        }
        cpa_commit();
    };

    issue(0);
    issue(1);

    for (int c = 0; c < nch; c++) {
        cpa_wait1();
        __syncthreads();
        issue(c + 2);

        const uint32_t sAH = sbase + (uint32_t)(c % 3) * STAGE_BYTES;
        const uint32_t sAL = sAH + 8192u;
        const uint32_t sBH = sAH + 16384u;
        const uint32_t sBL = sAH + 24576u;

        #pragma unroll
        for (int kk = 0; kk < 2; kk++) {
            uint32_t bb[8], aa[4];
            // ---- B hi fragments ----
            #pragma unroll
            for (int p = 0; p < 2; p++)
                ldsm4(&bb[p * 4], sBH + swf(wn * 32 + p * 16 + bro, 2 * kk + bco));
            // AH * BH
            #pragma unroll
            for (int mt = 0; mt < 4; mt++) {
                ldsm4(aa, sAH + swf(wm * 64 + mt * 16 + aro, 2 * kk + aco));
                mma16(acc[mt][0], aa, &bb[0]); mma16(acc[mt][1], aa, &bb[2]);
                mma16(acc[mt][2], aa, &bb[4]); mma16(acc[mt][3], aa, &bb[6]);
            }
            // AL * BH
            #pragma unroll
            for (int mt = 0; mt < 4; mt++) {
                ldsm4(aa, sAL + swf(wm * 64 + mt * 16 + aro, 2 * kk + aco));
                mma16(acc[mt][0], aa, &bb[0]); mma16(acc[mt][1], aa, &bb[2]);
                mma16(acc[mt][2], aa, &bb[4]); mma16(acc[mt][3], aa, &bb[6]);
            }
            // ---- B lo fragments ----
            #pragma unroll
            for (int p = 0; p < 2; p++)
                ldsm4(&bb[p * 4], sBL + swf(wn * 32 + p * 16 + bro, 2 * kk + bco));
            // AH * BL
            #pragma unroll
            for (int mt = 0; mt < 4; mt++) {
                ldsm4(aa, sAH + swf(wm * 64 + mt * 16 + aro, 2 * kk + aco));
                mma16(acc[mt][0], aa, &bb[0]); mma16(acc[mt][1], aa, &bb[2]);
                mma16(acc[mt][2], aa, &bb[4]); mma16(acc[mt][3], aa, &bb[6]);
            }
        }
    }

    // epilogue: c0,c1 at (r, c..c+1); c2,c3 at (r+8, c..c+1)
    #pragma unroll
    for (int mt = 0; mt < 4; mt++) {
        const int r = row0 + wm * 64 + mt * 16 + g;
        #pragma unroll
        for (int nt = 0; nt < 4; nt++) {
            const int c2 = col0 + wn * 32 + nt * 8 + 2 * tg;
            if (c2 < N) {
                float v0 = acc[mt][nt][0], v1 = acc[mt][nt][1];
                float v2 = acc[mt][nt][2], v3 = acc[mt][nt][3];
                if (EPI == 1) {
                    v0 += bias[c2]; v1 += bias[c2 + 1];
                    v2 += bias[c2]; v3 += bias[c2 + 1];
                    v0 = (v0 > 20.f) ? v0 : log1pf(__expf(v0));
                    v1 = (v1 > 20.f) ? v1 : log1pf(__expf(v1));
                    v2 = (v2 > 20.f) ? v2 : log1pf(__expf(v2));
                    v3 = (v3 > 20.f) ? v3 : log1pf(__expf(v3));
                } else if (EPI == 2) {
                    v0 += bias[c2]; v1 += bias[c2 + 1];
                    v2 += bias[c2]; v3 += bias[c2 + 1];
                }
                *(float2*)&C[(size_t)r * ldc + c2]       = make_float2(v0, v1);
                *(float2*)&C[(size_t)(r + 8) * ldc + c2] = make_float2(v2, v3);
            }
        }
    }
}

// ---------------------------------------------------------------------------
// hi/lo bf16 split kernels
// ---------------------------------------------------------------------------
__global__ void split_bf16(const float* __restrict__ src,
                           __nv_bfloat16* __restrict__ hi,
                           __nv_bfloat16* __restrict__ lo, int n4)
{
    const int i = blockIdx.x * 256 + threadIdx.x;
    if (i >= n4) return;
    const float4 v = ((const float4*)src)[i];
    __nv_bfloat162 h0, h1, l0, l1;
    h0.x = __float2bfloat16(v.x); l0.x = __float2bfloat16(v.x - __bfloat162float(h0.x));
    h0.y = __float2bfloat16(v.y); l0.y = __float2bfloat16(v.y - __bfloat162float(h0.y));
    h1.x = __float2bfloat16(v.z); l1.x = __float2bfloat16(v.z - __bfloat162float(h1.x));
    h1.y = __float2bfloat16(v.w); l1.y = __float2bfloat16(v.w - __bfloat162float(h1.y));
    ((__nv_bfloat162*)hi)[2*i]   = h0; ((__nv_bfloat162*)hi)[2*i+1] = h1;
    ((__nv_bfloat162*)lo)[2*i]   = l0; ((__nv_bfloat162*)lo)[2*i+1] = l1;
}

// split dt = g_xdbl[:, 0:128] (ld 160) -> compact 2048x128 planes
__global__ void split_dt_kernel()
{
    const int i = blockIdx.x * 256 + threadIdx.x;
    if (i >= MROWS * (DTRANK/4)) return;
    const int row = i >> 5, c4 = i & 31;
    const float4 v = *(const float4*)(g_xdbl + (size_t)row * XDBL_C + c4 * 4);
    __nv_bfloat162 h0, h1, l0, l1;
    h0.x = __float2bfloat16(v.x); l0.x = __float2bfloat16(v.x - __bfloat162float(h0.x));
    h0.y = __float2bfloat16(v.y); l0.y = __float2bfloat16(v.y - __bfloat162float(h0.y));
    h1.x = __float2bfloat16(v.z); l1.x = __float2bfloat16(v.z - __bfloat162float(h1.x));
    h1.y = __float2bfloat16(v.w); l1.y = __float2bfloat16(v.w - __bfloat162float(h1.y));
    const size_t o = (size_t)row * DTRANK + c4 * 4;
    *(__nv_bfloat162*)(g_dtH + o)     = h0; *(__nv_bfloat162*)(g_dtH + o + 2) = h1;
    *(__nv_bfloat162*)(g_dtL + o)     = l0; *(__nv_bfloat162*)(g_dtL + o + 2) = l1;
}

// deterministic split-K reduction
__global__ void reduce_splitk(int n)
{
    const int i = blockIdx.x * 256 + threadIdx.x;
    if (i < n) {
        float s = 0.f;
        #pragma unroll
        for (int z = 0; z < KSPLIT; z++) s += g_part[(size_t)z * n + i];
        g_xdbl[i] = s;
    }
}

// ---------------------------------------------------------------------------
// Depthwise causal conv (K=4) + SiLU, fused xc hi/lo split
// ---------------------------------------------------------------------------
__global__ void conv_silu_kernel(const float* __restrict__ conv_w,
                                 const float* __restrict__ conv_b)
{
    const int d  = blockIdx.x * 256 + threadIdx.x;
    const int b  = blockIdx.z;
    const int l0 = blockIdx.y * 128;

    const float w0 = conv_w[d*4+0], w1 = conv_w[d*4+1];
    const float w2 = conv_w[d*4+2], w3 = conv_w[d*4+3];
    const float cb = conv_b[d];

    const float* xb = g_xz + (size_t)b * LSEQ * E2 + d;
    const size_t ob = (size_t)b * LSEQ * DINNER + d;

    float x0 = (l0 >= 3) ? xb[(size_t)(l0-3) * E2] : 0.f;
    float x1 = (l0 >= 2) ? xb[(size_t)(l0-2) * E2] : 0.f;
    float x2 = (l0 >= 1) ? xb[(size_t)(l0-1) * E2] : 0.f;

    for (int l = l0; l < l0 + 128; l++) {
        float x3 = xb[(size_t)l * E2];
        float v  = fmaf(w0,x0, fmaf(w1,x1, fmaf(w2,x2, fmaf(w3,x3, cb))));
        float s  = 1.f / (1.f + __expf(-v));
        float o  = v * s;
        const size_t off = ob + (size_t)l * DINNER;
        g_xc[off] = o;
        __nv_bfloat16 h = __float2bfloat16(o);
        g_xcH[off] = h;
        g_xcL[off] = __float2bfloat16(o - __bfloat162float(h));
        x0 = x1; x1 = x2; x2 = x3;
    }
}

__global__ void conv_state_kernel(float* __restrict__ out)
{
    const int idx = blockIdx.x * 256 + threadIdx.x;
    const int b = idx >> 14;
    const int r = idx & 16383;
    const int d = r >> 2;
    const int k = r & 3;
    out[idx] = g_xz[((size_t)(b*LSEQ + (LSEQ - KCONV) + k)) * E2 + d];
}

// ---------------------------------------------------------------------------
// Chunked linear scan
// ---------------------------------------------------------------------------
__global__ void scan_phase1(const float* __restrict__ A_log)
{
    const int d = blockIdx.x * 256 + threadIdx.x;
    const int c = blockIdx.y, b = blockIdx.z;

    float a[DSTATE];
    #pragma unroll
    for (int n = 0; n < DSTATE; n++) a[n] = -__expf(A_log[d*DSTATE + n]);

    float s[DSTATE], ap[DSTATE];
    #pragma unroll
    for (int n = 0; n < DSTATE; n++) { s[n] = 0.f; ap[n] = 1.f; }

    const int mbase = b * LSEQ + c * CLEN;
    for (int t = 0; t < CLEN; t++) {
        const int m = mbase + t;
        const float dt = g_delta[(size_t)m * DINNER + d];
        const float u  = g_xc  [(size_t)m * DINNER + d];
        const float du = dt * u;
        const float* bp = g_xdbl + (size_t)m * XDBL_C + DTRANK;
        #pragma unroll
        for (int n = 0; n < DSTATE; n++) {
            float e = __expf(dt * a[n]);
            s[n]  = fmaf(e, s[n], du * __ldg(bp + n));
            ap[n] *= e;
        }
    }
    const size_t base = ((size_t)(b*NCHUNK + c) * DSTATE) * DINNER + d;
    #pragma unroll
    for (int n = 0; n < DSTATE; n++) {
        g_cA[base + (size_t)n * DINNER] = ap[n];
        g_cS[base + (size_t)n * DINNER] = s[n];
    }
}

__global__ void scan_phase2(float* __restrict__ last_state)
{
    const int d = blockIdx.x * 256 + threadIdx.x;
    const int n = blockIdx.y, b = blockIdx.z;
    float s = 0.f;
    #pragma unroll
    for (int c = 0; c < NCHUNK; c++) {
        const size_t off = ((size_t)(b*NCHUNK + c) * DSTATE + n) * DINNER + d;
        g_sini[off] = s;
        s = fmaf(g_cA[off], s, g_cS[off]);
    }
    last_state[((size_t)b * DINNER + d) * DSTATE + n] = s;
}

__global__ void scan_phase3(const float* __restrict__ A_log,
                            const float* __restrict__ Dvec)
{
    const int d = blockIdx.x * 256 + threadIdx.x;
    const int c = blockIdx.y, b = blockIdx.z;

    float a[DSTATE];
    #pragma unroll
    for (int n = 0; n < DSTATE; n++) a[n] = -__expf(A_log[d*DSTATE + n]);

    float s[DSTATE];
    const size_t base = ((size_t)(b*NCHUNK + c) * DSTATE) * DINNER + d;
    #pragma unroll
    for (int n = 0; n < DSTATE; n++) s[n] = g_sini[base + (size_t)n * DINNER];

    const float Dd = Dvec[d];
    const int mbase = b * LSEQ + c * CLEN;
    for (int t = 0; t < CLEN; t++) {
        const int m = mbase + t;
        const float dt = g_delta[(size_t)m * DINNER + d];
        const float u  = g_xc  [(size_t)m * DINNER + d];
        const float z  = g_xz  [(size_t)m * E2 + DINNER + d];
        const float du = dt * u;
        const float* bp = g_xdbl + (size_t)m * XDBL_C + DTRANK;
        const float* cp = bp + DSTATE;
        float yv = 0.f;
        #pragma unroll
        for (int n = 0; n < DSTATE; n++) {
            float e = __expf(dt * a[n]);
            s[n] = fmaf(e, s[n], du * __ldg(bp + n));
            yv   = fmaf(s[n], __ldg(cp + n), yv);
        }
        yv = fmaf(Dd, u, yv);
        const float sig = 1.f / (1.f + __expf(-z));
        const float yo  = yv * z * sig;
        const size_t off = (size_t)m * DINNER + d;
        __nv_bfloat16 h = __float2bfloat16(yo);
        g_yH[off] = h;
        g_yL[off] = __float2bfloat16(yo - __bfloat162float(h));
    }
}

// ---------------------------------------------------------------------------
extern "C" void kernel_launch(void* const* d_in, const int* in_sizes, int n_in,
                              void* d_out, int out_size)
{
    const float* hs     = (const float*)d_in[0];
    const float* W_in   = (const float*)d_in[1];
    const float* conv_w = (const float*)d_in[2];
    const float* conv_b = (const float*)d_in[3];
    const float* W_x    = (const float*)d_in[4];
    const float* W_dt   = (const float*)d_in[5];
    const float* b_dt   = (const float*)d_in[6];
    const float* A_log  = (const float*)d_in[7];
    const float* Dv     = (const float*)d_in[8];
    const float* W_out  = (const float*)d_in[9];
    const float* b_out  = (const float*)d_in[10];

    float* out        = (float*)d_out;
    float* conv_state = out + (size_t)BATCH * LSEQ * DMODEL;
    float* last_state = conv_state + (size_t)BATCH * DINNER * KCONV;

    float *p_xz, *p_xdbl, *p_delta, *p_part;
    cudaGetSymbolAddress((void**)&p_xz,    g_xz);
    cudaGetSymbolAddress((void**)&p_xdbl,  g_xdbl);
    cudaGetSymbolAddress((void**)&p_delta, g_delta);
    cudaGetSymbolAddress((void**)&p_part,  g_part);

    __nv_bfloat16 *hsH,*hsL,*winH,*winL,*xcH,*xcL,*wxH,*wxL,*dtH,*dtL,*wdtH,*wdtL,*yH,*yL,*woH,*woL;
    cudaGetSymbolAddress((void**)&hsH, g_hsH);   cudaGetSymbolAddress((void**)&hsL, g_hsL);
    cudaGetSymbolAddress((void**)&winH, g_winH); cudaGetSymbolAddress((void**)&winL, g_winL);
    cudaGetSymbolAddress((void**)&xcH, g_xcH);   cudaGetSymbolAddress((void**)&xcL, g_xcL);
    cudaGetSymbolAddress((void**)&wxH, g_wxH);   cudaGetSymbolAddress((void**)&wxL, g_wxL);
    cudaGetSymbolAddress((void**)&dtH, g_dtH);   cudaGetSymbolAddress((void**)&dtL, g_dtL);
    cudaGetSymbolAddress((void**)&wdtH, g_wdtH); cudaGetSymbolAddress((void**)&wdtL, g_wdtL);
    cudaGetSymbolAddress((void**)&yH, g_yH);     cudaGetSymbolAddress((void**)&yL, g_yL);
    cudaGetSymbolAddress((void**)&woH, g_woH);   cudaGetSymbolAddress((void**)&woL, g_woL);

    cudaFuncSetAttribute(bf_gemm<0>, cudaFuncAttributeMaxDynamicSharedMemorySize, G_SMEM);
    cudaFuncSetAttribute(bf_gemm<1>, cudaFuncAttributeMaxDynamicSharedMemorySize, G_SMEM);
    cudaFuncSetAttribute(bf_gemm<2>, cudaFuncAttributeMaxDynamicSharedMemorySize, G_SMEM);

    // 0) hi/lo splits of pure inputs
    split_bf16<<<(MROWS*DMODEL/4 + 255)/256, 256>>>(hs,    hsH,  hsL,  MROWS*DMODEL/4);
    split_bf16<<<(E2*DMODEL/4   + 255)/256, 256>>>(W_in,  winH, winL, E2*DMODEL/4);
    split_bf16<<<(XDBL_C*DINNER/4 + 255)/256, 256>>>(W_x,  wxH,  wxL,  XDBL_C*DINNER/4);
    split_bf16<<<(DINNER*DTRANK/4 + 255)/256, 256>>>(W_dt, wdtH, wdtL, DINNER*DTRANK/4);
    split_bf16<<<(DMODEL*DINNER/4 + 255)/256, 256>>>(W_out, woH, woL,  DMODEL*DINNER/4);

    // 1) xz[m][e] = hs[m,:] . W_in[e,:]      (2048 x 8192 x 2048)
    bf_gemm<0><<<dim3(E2/128, MROWS/128), 256, G_SMEM>>>(
        MROWS, E2, DMODEL, hsH, hsL, DMODEL, winH, winL, DMODEL, p_xz, E2, nullptr, 1);

    // 2) depthwise conv + SiLU (fused xc split); conv_state
    conv_silu_kernel<<<dim3(DINNER/256, LSEQ/128, BATCH), 256>>>(conv_w, conv_b);
    conv_state_kernel<<<dim3((BATCH*DINNER*KCONV)/256), 256>>>(conv_state);

    // 3) x_dbl[m][e] = xc[m,:] . W_x[e,:]    (2048 x 160 x 4096) split-K=8
    bf_gemm<0><<<dim3(2, MROWS/128, KSPLIT), 256, G_SMEM>>>(
        MROWS, XDBL_C, DINNER, xcH, xcL, DINNER, wxH, wxL, DINNER, p_part, XDBL_C, nullptr, KSPLIT);
    reduce_splitk<<<(MROWS*XDBL_C + 255)/256, 256>>>(MROWS * XDBL_C);
    split_dt_kernel<<<(MROWS*(DTRANK/4) + 255)/256, 256>>>();

    // 4) delta[m][d] = softplus(dt[m,:] . W_dt[d,:] + b_dt[d])   (2048 x 4096 x 128)
    bf_gemm<1><<<dim3(DINNER/128, MROWS/128), 256, G_SMEM>>>(
        MROWS, DINNER, DTRANK, dtH, dtL, DTRANK, wdtH, wdtL, DTRANK, p_delta, DINNER, b_dt, 1);

    // 5) chunked selective scan (+ gating, fused y split), emits last_state
    scan_phase1<<<dim3(DINNER/256, NCHUNK, BATCH), 256>>>(A_log);
    scan_phase2<<<dim3(DINNER/256, DSTATE, BATCH), 256>>>(last_state);
    scan_phase3<<<dim3(DINNER/256, NCHUNK, BATCH), 256>>>(A_log, Dv);

    // 6) out[m][e] = y[m,:] . W_out[e,:] + b_out[e]   (2048 x 2048 x 4096)
    bf_gemm<2><<<dim3(DMODEL/128, MROWS/128), 256, G_SMEM>>>(
        MROWS, DMODEL, DINNER, yH, yL, DINNER, woH, woL, DINNER, out, DMODEL, b_out, 1);
}